// round 1
// baseline (speedup 1.0000x reference)
#include <cuda_runtime.h>
#include <cstdint>

#define HH 256
#define WW 256
#define HWP 65536
#define CCH 6
#define NSP 500
#define NIT 5
#define BSZ (NSP*CCH)

// ---------------- static device scratch (no allocations allowed) ----------------
__device__ float  g_wts[81 * HWP];        // bilateral weights, tap-major [t][pix]
__device__ float  g_bilnorm[HWP];         // sum of bilateral weights per pixel
__device__ float2 g_p[2 * 3 * HWP];       // double-buffered softmax p, 3 float2 planes
__device__ float  g_B[NIT * BSZ];         // per-iteration superpixel log-sums
__device__ float  g_k[19];                // 1D gaussian kernel (theta_gamma=3, r=9)
__device__ float  g_S[WW];                // 1D normalization sums
__device__ float  g_M1[36];               // comp @ sk
__device__ float  g_M2[36];               // comp @ bk

// ---------------- tiny prep: kernels, norms, folded 6x6 matrices, zero B -------
__global__ void prep_kernel(const float* __restrict__ sk,
                            const float* __restrict__ bk,
                            const float* __restrict__ comp) {
    int t = threadIdx.x;
    for (int i = t; i < NIT * BSZ; i += blockDim.x) g_B[i] = 0.f;
    if (t < 19) {
        float d = (float)(t - 9);
        g_k[t] = __expf(-d * d * (1.f / 18.f));
    }
    if (t < WW) {
        float s = 0.f;
        for (int d = -9; d <= 9; ++d) {
            int j = t + d;
            if (j >= 0 && j < WW) s += __expf(-(float)(d * d) * (1.f / 18.f));
        }
        g_S[t] = s;
    }
    if (t < 36) {
        int i = t / 6, j = t % 6;
        float m1 = 0.f, m2 = 0.f;
        for (int kk = 0; kk < 6; ++kk) {
            m1 += comp[i * 6 + kk] * sk[kk * 6 + j];
            m2 += comp[i * 6 + kk] * bk[kk * 6 + j];
        }
        g_M1[t] = m1;
        g_M2[t] = m2;
    }
}

// ------------- precompute: bilateral weights + norm, softmax(u) -> p0, B[0] ----
__global__ void __launch_bounds__(256) precompute_kernel(
        const float* __restrict__ rgb, const float* __restrict__ u,
        const int* __restrict__ spmap) {
    int x = threadIdx.x, y = blockIdx.x;
    int pix = y * WW + x;

    float r0 = rgb[pix * 3 + 0];
    float g0 = rgb[pix * 3 + 1];
    float b0 = rgb[pix * 3 + 2];
    float norm = 0.f;

    #pragma unroll 1
    for (int dy = -4; dy <= 4; ++dy) {
        int ny = y + dy;
        #pragma unroll
        for (int dx = -4; dx <= 4; ++dx) {
            int nx = x + dx;
            int t = (dy + 4) * 9 + (dx + 4);
            float w = 0.f;
            if ((unsigned)ny < (unsigned)HH && (unsigned)nx < (unsigned)WW) {
                int np = ny * WW + nx;
                float dr = r0 - rgb[np * 3 + 0];
                float dg = g0 - rgb[np * 3 + 1];
                float db = b0 - rgb[np * 3 + 2];
                float d2 = dr * dr + dg * dg + db * db;
                // combined spatial (2*160^2=51200) + color (2*3^2=18) exponent
                float arg = -((float)(dy * dy + dx * dx) * (1.f / 51200.f)
                              + d2 * (1.f / 18.f));
                if (arg > -30.f) w = __expf(arg);   // below: < 1e-13, underflow-equal
            }
            g_wts[t * HWP + pix] = w;
            norm += w;
        }
    }
    g_bilnorm[pix] = norm;

    // p0 = softmax(unaries) per pixel over C
    float q[6];
    #pragma unroll
    for (int c = 0; c < 6; ++c) q[c] = u[pix * 6 + c];
    float m = q[0];
    #pragma unroll
    for (int c = 1; c < 6; ++c) m = fmaxf(m, q[c]);
    float e[6], s = 0.f;
    #pragma unroll
    for (int c = 0; c < 6; ++c) { e[c] = __expf(q[c] - m); s += e[c]; }
    float inv = __fdividef(1.f, s);
    float pv[6];
    #pragma unroll
    for (int c = 0; c < 6; ++c) pv[c] = e[c] * inv;

    g_p[0 * HWP + pix] = make_float2(pv[0], pv[1]);
    g_p[1 * HWP + pix] = make_float2(pv[2], pv[3]);
    g_p[2 * HWP + pix] = make_float2(pv[4], pv[5]);

    // NOTE the reference's transpose quirk: pixel (y,x) uses sp_map[x, y]
    int spid = spmap[x * WW + y];
    #pragma unroll
    for (int c = 0; c < 6; ++c)
        atomicAdd(&g_B[spid * 6 + c], __logf(pv[c] + 1e-5f));
}

// ------------- fused mean-field iteration: one block per image row ------------
__global__ void __launch_bounds__(256) iter_kernel(
        int iter,
        const float* __restrict__ u, const int* __restrict__ spmap,
        const float* __restrict__ loww, const float* __restrict__ highw,
        float* __restrict__ out) {
    __shared__ float sh[256 * 7];   // stride 7 -> conflict-free
    int x = threadIdx.x, y = blockIdx.x;
    int pix = y * WW + x;
    const float2* p = g_p + (size_t)(iter & 1) * 3 * HWP;

    // ---- spatial filter, vertical 19-tap ----
    float a0 = 0, a1 = 0, a2 = 0, a3 = 0, a4 = 0, a5 = 0;
    #pragma unroll 1
    for (int dy = -9; dy <= 9; ++dy) {
        int ny = y + dy;
        if ((unsigned)ny < (unsigned)HH) {
            float w = g_k[dy + 9];
            int np = ny * WW + x;
            float2 v0 = p[np], v1 = p[HWP + np], v2 = p[2 * HWP + np];
            a0 = fmaf(w, v0.x, a0); a1 = fmaf(w, v0.y, a1);
            a2 = fmaf(w, v1.x, a2); a3 = fmaf(w, v1.y, a3);
            a4 = fmaf(w, v2.x, a4); a5 = fmaf(w, v2.y, a5);
        }
    }
    sh[x * 7 + 0] = a0; sh[x * 7 + 1] = a1; sh[x * 7 + 2] = a2;
    sh[x * 7 + 3] = a3; sh[x * 7 + 4] = a4; sh[x * 7 + 5] = a5;
    __syncthreads();

    // ---- horizontal 19-tap from shared ----
    float s0 = 0, s1 = 0, s2 = 0, s3 = 0, s4 = 0, s5 = 0;
    #pragma unroll 1
    for (int dx = -9; dx <= 9; ++dx) {
        int nx = x + dx;
        if ((unsigned)nx < (unsigned)WW) {
            float w = g_k[dx + 9];
            const float* qv = &sh[nx * 7];
            s0 = fmaf(w, qv[0], s0); s1 = fmaf(w, qv[1], s1);
            s2 = fmaf(w, qv[2], s2); s3 = fmaf(w, qv[3], s3);
            s4 = fmaf(w, qv[4], s4); s5 = fmaf(w, qv[5], s5);
        }
    }
    float rn = __fdividef(1.f, g_S[y] * g_S[x]);
    s0 *= rn; s1 *= rn; s2 *= rn; s3 *= rn; s4 *= rn; s5 *= rn;

    // ---- bilateral 81-tap ----
    float b0 = 0, b1 = 0, b2 = 0, b3 = 0, b4 = 0, b5 = 0;
    const float* wb = g_wts + pix;
    if (x >= 4 && x < WW - 4 && y >= 4 && y < HH - 4) {
        #pragma unroll 1
        for (int dy = -4; dy <= 4; ++dy) {
            int np = (y + dy) * WW + x;
            const float* wr = wb + (size_t)(dy + 4) * 9 * HWP;
            #pragma unroll
            for (int dx = -4; dx <= 4; ++dx) {
                float w = wr[(size_t)(dx + 4) * HWP];
                float2 v0 = p[np + dx], v1 = p[HWP + np + dx], v2 = p[2 * HWP + np + dx];
                b0 = fmaf(w, v0.x, b0); b1 = fmaf(w, v0.y, b1);
                b2 = fmaf(w, v1.x, b2); b3 = fmaf(w, v1.y, b3);
                b4 = fmaf(w, v2.x, b4); b5 = fmaf(w, v2.y, b5);
            }
        }
    } else {
        #pragma unroll 1
        for (int dy = -4; dy <= 4; ++dy) {
            int ny = y + dy;
            const float* wr = wb + (size_t)(dy + 4) * 9 * HWP;
            if ((unsigned)ny < (unsigned)HH) {
                int np = ny * WW + x;
                #pragma unroll
                for (int dx = -4; dx <= 4; ++dx) {
                    int nx = x + dx;
                    if ((unsigned)nx < (unsigned)WW) {
                        float w = wr[(size_t)(dx + 4) * HWP];
                        float2 v0 = p[np + dx], v1 = p[HWP + np + dx], v2 = p[2 * HWP + np + dx];
                        b0 = fmaf(w, v0.x, b0); b1 = fmaf(w, v0.y, b1);
                        b2 = fmaf(w, v1.x, b2); b3 = fmaf(w, v1.y, b3);
                        b4 = fmaf(w, v2.x, b4); b5 = fmaf(w, v2.y, b5);
                    }
                }
            }
        }
    }
    float rbn = __fdividef(1.f, g_bilnorm[pix]);
    b0 *= rbn; b1 *= rbn; b2 *= rbn; b3 *= rbn; b4 *= rbn; b5 *= rbn;

    // ---- pairwise = (comp@sk)@s + (comp@bk)@b ----
    float sv[6] = {s0, s1, s2, s3, s4, s5};
    float bv[6] = {b0, b1, b2, b3, b4, b5};
    float pw[6];
    #pragma unroll
    for (int i = 0; i < 6; ++i) {
        float acc = 0.f;
        #pragma unroll
        for (int j = 0; j < 6; ++j)
            acc += g_M1[i * 6 + j] * sv[j] + g_M2[i * 6 + j] * bv[j];
        pw[i] = acc;
    }

    // ---- superpixel update (transposed sp indexing, per reference) ----
    int spid = spmap[x * WW + y];
    float2 pc0 = p[pix], pc1 = p[HWP + pix], pc2 = p[2 * HWP + pix];
    float ps[6] = {pc0.x, pc0.y, pc1.x, pc1.y, pc2.x, pc2.y};
    float hw = highw[0];
    const float* Bt = g_B + iter * BSZ + spid * 6;
    float qn[6];
    #pragma unroll
    for (int c = 0; c < 6; ++c) {
        float lq = __logf(ps[c] + 1e-5f);
        float first = __expf(Bt[c] - lq);
        float spu = loww[c] * first + hw * (1.f - first);
        qn[c] = u[pix * 6 + c] - pw[c] - spu;
    }

    if (iter == NIT - 1) {
        #pragma unroll
        for (int c = 0; c < 6; ++c) out[pix * 6 + c] = qn[c];
    } else {
        // softmax(qn) -> next p buffer, accumulate B[iter+1]
        float2* pn = g_p + (size_t)((iter + 1) & 1) * 3 * HWP;
        float m = qn[0];
        #pragma unroll
        for (int c = 1; c < 6; ++c) m = fmaxf(m, qn[c]);
        float e[6], ssum = 0.f;
        #pragma unroll
        for (int c = 0; c < 6; ++c) { e[c] = __expf(qn[c] - m); ssum += e[c]; }
        float inv = __fdividef(1.f, ssum);
        float pv[6];
        #pragma unroll
        for (int c = 0; c < 6; ++c) pv[c] = e[c] * inv;
        pn[pix]           = make_float2(pv[0], pv[1]);
        pn[HWP + pix]     = make_float2(pv[2], pv[3]);
        pn[2 * HWP + pix] = make_float2(pv[4], pv[5]);
        float* Bn = g_B + (iter + 1) * BSZ + spid * 6;
        #pragma unroll
        for (int c = 0; c < 6; ++c)
            atomicAdd(&Bn[c], __logf(pv[c] + 1e-5f));
    }
}

extern "C" void kernel_launch(void* const* d_in, const int* in_sizes, int n_in,
                              void* d_out, int out_size) {
    const float* unaries = (const float*)d_in[0];
    const float* rgb     = (const float*)d_in[1];
    const int*   spmap   = (const int*)d_in[2];
    const float* sk      = (const float*)d_in[3];
    const float* bk      = (const float*)d_in[4];
    const float* comp    = (const float*)d_in[5];
    const float* loww    = (const float*)d_in[6];
    const float* highw   = (const float*)d_in[7];
    float* out = (float*)d_out;

    prep_kernel<<<1, 256>>>(sk, bk, comp);
    precompute_kernel<<<HH, WW>>>(rgb, unaries, spmap);
    for (int it = 0; it < NIT; ++it) {
        iter_kernel<<<HH, WW>>>(it, unaries, spmap, loww, highw, out);
    }
}

// round 2
// speedup vs baseline: 1.0011x; 1.0011x over previous
#include <cuda_runtime.h>
#include <cstdint>

#define HH 256
#define WW 256
#define HWP 65536
#define CCH 6
#define NSP 500
#define NIT 5
#define BSZ (NSP*CCH)

// ---------------- static device scratch (no allocations allowed) ----------------
__device__ float  g_wts[81 * HWP];        // bilateral weights, tap-major [t][pix]
__device__ float  g_bilnorm[HWP];         // sum of bilateral weights per pixel
__device__ float2 g_p[2 * 3 * HWP];       // double-buffered softmax p, 3 float2 planes
__device__ float  g_B[NIT * BSZ];         // per-iteration superpixel log-sums
__device__ float  g_k[19];                // 1D gaussian kernel (theta_gamma=3, r=9)
__device__ float  g_S[WW];                // 1D normalization sums
__device__ float  g_M1[36];               // comp @ sk
__device__ float  g_M2[36];               // comp @ bk

// ---------------- tiny prep: kernels, norms, folded 6x6 matrices, zero B -------
__global__ void prep_kernel(const float* __restrict__ sk,
                            const float* __restrict__ bk,
                            const float* __restrict__ comp) {
    int t = threadIdx.x;
    for (int i = t; i < NIT * BSZ; i += blockDim.x) g_B[i] = 0.f;
    if (t < 19) {
        float d = (float)(t - 9);
        g_k[t] = __expf(-d * d * (1.f / 18.f));
    }
    if (t < WW) {
        float s = 0.f;
        for (int d = -9; d <= 9; ++d) {
            int j = t + d;
            if (j >= 0 && j < WW) s += __expf(-(float)(d * d) * (1.f / 18.f));
        }
        g_S[t] = s;
    }
    if (t < 36) {
        int i = t / 6, j = t % 6;
        float m1 = 0.f, m2 = 0.f;
        for (int kk = 0; kk < 6; ++kk) {
            m1 += comp[i * 6 + kk] * sk[kk * 6 + j];
            m2 += comp[i * 6 + kk] * bk[kk * 6 + j];
        }
        g_M1[t] = m1;
        g_M2[t] = m2;
    }
}

// ------------- precompute: bilateral weights + norm, softmax(u) -> p0, B[0] ----
__global__ void __launch_bounds__(256) precompute_kernel(
        const float* __restrict__ rgb, const float* __restrict__ u,
        const int* __restrict__ spmap) {
    int x = threadIdx.x, y = blockIdx.x;
    int pix = y * WW + x;

    float r0 = rgb[pix * 3 + 0];
    float g0 = rgb[pix * 3 + 1];
    float b0 = rgb[pix * 3 + 2];
    float norm = 0.f;

    #pragma unroll 1
    for (int dy = -4; dy <= 4; ++dy) {
        int ny = y + dy;
        #pragma unroll
        for (int dx = -4; dx <= 4; ++dx) {
            int nx = x + dx;
            int t = (dy + 4) * 9 + (dx + 4);
            float w = 0.f;
            if ((unsigned)ny < (unsigned)HH && (unsigned)nx < (unsigned)WW) {
                int np = ny * WW + nx;
                float dr = r0 - rgb[np * 3 + 0];
                float dg = g0 - rgb[np * 3 + 1];
                float db = b0 - rgb[np * 3 + 2];
                float d2 = dr * dr + dg * dg + db * db;
                // combined spatial (2*160^2=51200) + color (2*3^2=18) exponent
                float arg = -((float)(dy * dy + dx * dx) * (1.f / 51200.f)
                              + d2 * (1.f / 18.f));
                if (arg > -30.f) w = __expf(arg);   // below: < 1e-13, underflow-equal
            }
            g_wts[t * HWP + pix] = w;
            norm += w;
        }
    }
    g_bilnorm[pix] = norm;

    // p0 = softmax(unaries) per pixel over C
    float q[6];
    #pragma unroll
    for (int c = 0; c < 6; ++c) q[c] = u[pix * 6 + c];
    float m = q[0];
    #pragma unroll
    for (int c = 1; c < 6; ++c) m = fmaxf(m, q[c]);
    float e[6], s = 0.f;
    #pragma unroll
    for (int c = 0; c < 6; ++c) { e[c] = __expf(q[c] - m); s += e[c]; }
    float inv = __fdividef(1.f, s);
    float pv[6];
    #pragma unroll
    for (int c = 0; c < 6; ++c) pv[c] = e[c] * inv;

    g_p[0 * HWP + pix] = make_float2(pv[0], pv[1]);
    g_p[1 * HWP + pix] = make_float2(pv[2], pv[3]);
    g_p[2 * HWP + pix] = make_float2(pv[4], pv[5]);

    // NOTE the reference's transpose quirk: pixel (y,x) uses sp_map[x, y]
    int spid = spmap[x * WW + y];
    #pragma unroll
    for (int c = 0; c < 6; ++c)
        atomicAdd(&g_B[spid * 6 + c], __logf(pv[c] + 1e-5f));
}

// ------------- fused mean-field iteration: one block per image row ------------
__global__ void __launch_bounds__(256) iter_kernel(
        int iter,
        const float* __restrict__ u, const int* __restrict__ spmap,
        const float* __restrict__ loww, const float* __restrict__ highw,
        float* __restrict__ out) {
    __shared__ float sh[256 * 7];   // stride 7 -> conflict-free
    int x = threadIdx.x, y = blockIdx.x;
    int pix = y * WW + x;
    const float2* p = g_p + (size_t)(iter & 1) * 3 * HWP;

    // ---- spatial filter, vertical 19-tap ----
    float a0 = 0, a1 = 0, a2 = 0, a3 = 0, a4 = 0, a5 = 0;
    #pragma unroll 1
    for (int dy = -9; dy <= 9; ++dy) {
        int ny = y + dy;
        if ((unsigned)ny < (unsigned)HH) {
            float w = g_k[dy + 9];
            int np = ny * WW + x;
            float2 v0 = p[np], v1 = p[HWP + np], v2 = p[2 * HWP + np];
            a0 = fmaf(w, v0.x, a0); a1 = fmaf(w, v0.y, a1);
            a2 = fmaf(w, v1.x, a2); a3 = fmaf(w, v1.y, a3);
            a4 = fmaf(w, v2.x, a4); a5 = fmaf(w, v2.y, a5);
        }
    }
    sh[x * 7 + 0] = a0; sh[x * 7 + 1] = a1; sh[x * 7 + 2] = a2;
    sh[x * 7 + 3] = a3; sh[x * 7 + 4] = a4; sh[x * 7 + 5] = a5;
    __syncthreads();

    // ---- horizontal 19-tap from shared ----
    float s0 = 0, s1 = 0, s2 = 0, s3 = 0, s4 = 0, s5 = 0;
    #pragma unroll 1
    for (int dx = -9; dx <= 9; ++dx) {
        int nx = x + dx;
        if ((unsigned)nx < (unsigned)WW) {
            float w = g_k[dx + 9];
            const float* qv = &sh[nx * 7];
            s0 = fmaf(w, qv[0], s0); s1 = fmaf(w, qv[1], s1);
            s2 = fmaf(w, qv[2], s2); s3 = fmaf(w, qv[3], s3);
            s4 = fmaf(w, qv[4], s4); s5 = fmaf(w, qv[5], s5);
        }
    }
    float rn = __fdividef(1.f, g_S[y] * g_S[x]);
    s0 *= rn; s1 *= rn; s2 *= rn; s3 *= rn; s4 *= rn; s5 *= rn;

    // ---- bilateral 81-tap ----
    float b0 = 0, b1 = 0, b2 = 0, b3 = 0, b4 = 0, b5 = 0;
    const float* wb = g_wts + pix;
    if (x >= 4 && x < WW - 4 && y >= 4 && y < HH - 4) {
        #pragma unroll 1
        for (int dy = -4; dy <= 4; ++dy) {
            int np = (y + dy) * WW + x;
            const float* wr = wb + (size_t)(dy + 4) * 9 * HWP;
            #pragma unroll
            for (int dx = -4; dx <= 4; ++dx) {
                float w = wr[(size_t)(dx + 4) * HWP];
                float2 v0 = p[np + dx], v1 = p[HWP + np + dx], v2 = p[2 * HWP + np + dx];
                b0 = fmaf(w, v0.x, b0); b1 = fmaf(w, v0.y, b1);
                b2 = fmaf(w, v1.x, b2); b3 = fmaf(w, v1.y, b3);
                b4 = fmaf(w, v2.x, b4); b5 = fmaf(w, v2.y, b5);
            }
        }
    } else {
        #pragma unroll 1
        for (int dy = -4; dy <= 4; ++dy) {
            int ny = y + dy;
            const float* wr = wb + (size_t)(dy + 4) * 9 * HWP;
            if ((unsigned)ny < (unsigned)HH) {
                int np = ny * WW + x;
                #pragma unroll
                for (int dx = -4; dx <= 4; ++dx) {
                    int nx = x + dx;
                    if ((unsigned)nx < (unsigned)WW) {
                        float w = wr[(size_t)(dx + 4) * HWP];
                        float2 v0 = p[np + dx], v1 = p[HWP + np + dx], v2 = p[2 * HWP + np + dx];
                        b0 = fmaf(w, v0.x, b0); b1 = fmaf(w, v0.y, b1);
                        b2 = fmaf(w, v1.x, b2); b3 = fmaf(w, v1.y, b3);
                        b4 = fmaf(w, v2.x, b4); b5 = fmaf(w, v2.y, b5);
                    }
                }
            }
        }
    }
    float rbn = __fdividef(1.f, g_bilnorm[pix]);
    b0 *= rbn; b1 *= rbn; b2 *= rbn; b3 *= rbn; b4 *= rbn; b5 *= rbn;

    // ---- pairwise = (comp@sk)@s + (comp@bk)@b ----
    float sv[6] = {s0, s1, s2, s3, s4, s5};
    float bv[6] = {b0, b1, b2, b3, b4, b5};
    float pw[6];
    #pragma unroll
    for (int i = 0; i < 6; ++i) {
        float acc = 0.f;
        #pragma unroll
        for (int j = 0; j < 6; ++j)
            acc += g_M1[i * 6 + j] * sv[j] + g_M2[i * 6 + j] * bv[j];
        pw[i] = acc;
    }

    // ---- superpixel update (transposed sp indexing, per reference) ----
    int spid = spmap[x * WW + y];
    float2 pc0 = p[pix], pc1 = p[HWP + pix], pc2 = p[2 * HWP + pix];
    float ps[6] = {pc0.x, pc0.y, pc1.x, pc1.y, pc2.x, pc2.y};
    float hw = highw[0];
    const float* Bt = g_B + iter * BSZ + spid * 6;
    float qn[6];
    #pragma unroll
    for (int c = 0; c < 6; ++c) {
        float lq = __logf(ps[c] + 1e-5f);
        float first = __expf(Bt[c] - lq);
        float spu = loww[c] * first + hw * (1.f - first);
        qn[c] = u[pix * 6 + c] - pw[c] - spu;
    }

    if (iter == NIT - 1) {
        #pragma unroll
        for (int c = 0; c < 6; ++c) out[pix * 6 + c] = qn[c];
    } else {
        // softmax(qn) -> next p buffer, accumulate B[iter+1]
        float2* pn = g_p + (size_t)((iter + 1) & 1) * 3 * HWP;
        float m = qn[0];
        #pragma unroll
        for (int c = 1; c < 6; ++c) m = fmaxf(m, qn[c]);
        float e[6], ssum = 0.f;
        #pragma unroll
        for (int c = 0; c < 6; ++c) { e[c] = __expf(qn[c] - m); ssum += e[c]; }
        float inv = __fdividef(1.f, ssum);
        float pv[6];
        #pragma unroll
        for (int c = 0; c < 6; ++c) pv[c] = e[c] * inv;
        pn[pix]           = make_float2(pv[0], pv[1]);
        pn[HWP + pix]     = make_float2(pv[2], pv[3]);
        pn[2 * HWP + pix] = make_float2(pv[4], pv[5]);
        float* Bn = g_B + (iter + 1) * BSZ + spid * 6;
        #pragma unroll
        for (int c = 0; c < 6; ++c)
            atomicAdd(&Bn[c], __logf(pv[c] + 1e-5f));
    }
}

extern "C" void kernel_launch(void* const* d_in, const int* in_sizes, int n_in,
                              void* d_out, int out_size) {
    const float* unaries = (const float*)d_in[0];
    const float* rgb     = (const float*)d_in[1];
    const int*   spmap   = (const int*)d_in[2];
    const float* sk      = (const float*)d_in[3];
    const float* bk      = (const float*)d_in[4];
    const float* comp    = (const float*)d_in[5];
    const float* loww    = (const float*)d_in[6];
    const float* highw   = (const float*)d_in[7];
    float* out = (float*)d_out;

    prep_kernel<<<1, 256>>>(sk, bk, comp);
    precompute_kernel<<<HH, WW>>>(rgb, unaries, spmap);
    for (int it = 0; it < NIT; ++it) {
        iter_kernel<<<HH, WW>>>(it, unaries, spmap, loww, highw, out);
    }
}